// round 15
// baseline (speedup 1.0000x reference)
#include <cuda_runtime.h>
#include <cuda_bf16.h>
#include <cstdint>

#define BATCH 4
#define CH    512
#define NPIX  4096
#define MID   64

// ---------------- global scratch ----------------
// Fragment-packed operands: one uint4 per lane per fragment.
__device__ uint4 g_Qf[BATCH * 256 * 4 * 32];        // (b, qb16, ks4, lane)  A-frag
__device__ uint4 g_Kf[BATCH * 256 * 4 * 32];        // (b, jb16, ks4, lane)  B-frag
__device__ uint4 g_Vf[BATCH * 32 * 256 * 32];       // (b, db16, kb16, lane) B-frag
__device__ __nv_bfloat16 g_xb[BATCH * CH * NPIX];   // bf16 copy of x
__device__ __nv_bfloat16 g_Wb[640 * CH];            // rows: 0-63 Wq, 64-127 Wk, 128-639 Wv
__device__ float         g_bias[640];

// ---------------- helpers ----------------
__device__ __forceinline__ uint32_t smem_u32(const void* p) {
    uint32_t a;
    asm("{ .reg .u64 t; cvta.to.shared.u64 t, %1; cvt.u32.u64 %0, t; }" : "=r"(a) : "l"(p));
    return a;
}
__device__ __forceinline__ void ldm_x4(uint32_t r[4], uint32_t addr) {
    asm volatile("ldmatrix.sync.aligned.m8n8.x4.shared.b16 {%0,%1,%2,%3}, [%4];"
                 : "=r"(r[0]), "=r"(r[1]), "=r"(r[2]), "=r"(r[3]) : "r"(addr));
}
__device__ __forceinline__ void ldm_x4t(uint32_t r[4], uint32_t addr) {
    asm volatile("ldmatrix.sync.aligned.m8n8.x4.trans.shared.b16 {%0,%1,%2,%3}, [%4];"
                 : "=r"(r[0]), "=r"(r[1]), "=r"(r[2]), "=r"(r[3]) : "r"(addr));
}
__device__ __forceinline__ void mma16816(float* c, const uint32_t* a, uint32_t b0, uint32_t b1) {
    asm volatile("mma.sync.aligned.m16n8k16.row.col.f32.bf16.bf16.f32 "
                 "{%0,%1,%2,%3}, {%4,%5,%6,%7}, {%8,%9}, {%0,%1,%2,%3};"
                 : "+f"(c[0]), "+f"(c[1]), "+f"(c[2]), "+f"(c[3])
                 : "r"(a[0]), "r"(a[1]), "r"(a[2]), "r"(a[3]), "r"(b0), "r"(b1));
}
__device__ __forceinline__ uint32_t bpack(float a, float b) {
    __nv_bfloat162 h = __floats2bfloat162_rn(a, b);
    return *(uint32_t*)&h;
}
__device__ __forceinline__ void cp16(uint32_t dst, const void* src) {
    asm volatile("cp.async.cg.shared.global [%0], [%1], 16;" :: "r"(dst), "l"(src));
}
#define CP_COMMIT() asm volatile("cp.async.commit_group;" ::: "memory")
#define CP_WAIT0()  asm volatile("cp.async.wait_group 0;" ::: "memory")
#define CP_WAIT1()  asm volatile("cp.async.wait_group 1;" ::: "memory")
#define CP_WAIT2()  asm volatile("cp.async.wait_group 2;" ::: "memory")

// =================================================================
// Kernel 0a: convert x -> bf16 (8 elems / thread)
// =================================================================
__global__ __launch_bounds__(256) void conv_x_kernel(const float* __restrict__ x)
{
    size_t i = ((size_t)blockIdx.x * 256 + threadIdx.x) * 8;
    float4 a = *(const float4*)&x[i];
    float4 c = *(const float4*)&x[i + 4];
    *(uint4*)&g_xb[i] = make_uint4(bpack(a.x, a.y), bpack(a.z, a.w),
                                   bpack(c.x, c.y), bpack(c.z, c.w));
}

// =================================================================
// Kernel 0b: pack W -> g_Wb (bf16) + g_bias
// =================================================================
__global__ __launch_bounds__(256) void conv_w_kernel(
    const float* __restrict__ Wq, const float* __restrict__ bq,
    const float* __restrict__ Wk, const float* __restrict__ bk,
    const float* __restrict__ Wv, const float* __restrict__ bv)
{
    int gid = blockIdx.x * 256 + threadIdx.x;
    size_t base = (size_t)gid * 8;
    int row = (int)(base >> 9), k = (int)(base & 511);
    const float* src;
    if (row < 64)       src = Wq + row * CH + k;
    else if (row < 128) src = Wk + (row - 64) * CH + k;
    else                src = Wv + (row - 128) * CH + k;
    float4 a = *(const float4*)src;
    float4 c = *(const float4*)(src + 4);
    *(uint4*)&g_Wb[base] = make_uint4(bpack(a.x, a.y), bpack(a.z, a.w),
                                      bpack(c.x, c.y), bpack(c.z, c.w));
    if (gid < 640)
        g_bias[gid] = (gid < 64) ? bq[gid] : (gid < 128) ? bk[gid - 64] : bv[gid - 128];
}

// =================================================================
// Kernel 1: QKV projection (bf16 mma.sync GEMM), epilogue writes
// fragment-packed Q/K/V directly.  (unchanged — verified)
// =================================================================
#define PW_STR 144
#define PX_STR 272

__global__ __launch_bounds__(256) void proj_mma_kernel()
{
    __shared__ __align__(16) char ps[9216 + 17408];
    char* Wt = ps;
    char* Xt = ps + 9216;
    const uint32_t smb = smem_u32(ps);
    const int tid = threadIdx.x, lane = tid & 31, wid = tid >> 5;
    const int mg = wid >> 1, nh = wid & 1;
    const int n0 = blockIdx.x * 128;
    const int rg = blockIdx.y;          // 0=Q rows, 1=K rows, 2-9=V rows
    const int b  = blockIdx.z;

    float fc[8][4];
#pragma unroll
    for (int nb = 0; nb < 8; nb++)
#pragma unroll
        for (int e = 0; e < 4; e++) fc[nb][e] = 0.f;

    const uint32_t aoffA  = (lane & 15) * PW_STR + (lane >> 4) * 16;
    const uint32_t aoffBT = ((lane & 7) + ((lane >> 3) & 1) * 8) * PX_STR + (lane >> 4) * 16;

    for (int kc = 0; kc < CH; kc += 64) {
        __syncthreads();
        for (int idx = tid; idx < 512; idx += 256) {
            int row = idx >> 3, c16 = idx & 7;
            *(uint4*)(Wt + row * PW_STR + c16 * 16) =
                *(const uint4*)&g_Wb[(size_t)(rg * 64 + row) * CH + kc + c16 * 8];
        }
        for (int idx = tid; idx < 1024; idx += 256) {
            int row = idx >> 4, c16 = idx & 15;
            *(uint4*)(Xt + row * PX_STR + c16 * 16) =
                *(const uint4*)&g_xb[((size_t)b * CH + kc + row) * NPIX + n0 + c16 * 8];
        }
        __syncthreads();
#pragma unroll
        for (int ks = 0; ks < 4; ks++) {
            uint32_t aW[4];
            ldm_x4(aW, smb + (mg * 16) * PW_STR + ks * 32 + aoffA);
#pragma unroll
            for (int nb = 0; nb < 4; nb++) {
                uint32_t bx[4];
                ldm_x4t(bx, smb + 9216 + (ks * 16) * PX_STR + (nh * 64 + nb * 16) * 2 + aoffBT);
                mma16816(fc[2 * nb],     aW, bx[0], bx[1]);
                mma16816(fc[2 * nb + 1], aW, bx[2], bx[3]);
            }
        }
    }

    const int mr = mg * 16 + (lane >> 2);
    const float b0 = g_bias[rg * 64 + mr], b1 = g_bias[rg * 64 + mr + 8];

    if (rg >= 2) {
        const int db = (rg - 2) * 4 + mg;
#pragma unroll
        for (int jg = 0; jg < 4; jg++) {
            int nb0 = 2 * jg, nb1 = 2 * jg + 1;
            uint4 v;
            v.x = bpack(fc[nb0][0] + b0, fc[nb0][1] + b0);
            v.y = bpack(fc[nb1][0] + b0, fc[nb1][1] + b0);
            v.z = bpack(fc[nb0][2] + b1, fc[nb0][3] + b1);
            v.w = bpack(fc[nb1][2] + b1, fc[nb1][3] + b1);
            int kb = blockIdx.x * 8 + nh * 4 + jg;
            g_Vf[(((size_t)b * 32 + db) * 256 + kb) * 32 + lane] = v;
        }
    } else {
        __syncthreads();
        __nv_bfloat16* st = (__nv_bfloat16*)ps;
#pragma unroll
        for (int nb = 0; nb < 8; nb++) {
            int nl = nh * 64 + nb * 8 + (lane & 3) * 2;
            st[nl * 72 + mr]           = __float2bfloat16(fc[nb][0] + b0);
            st[(nl + 1) * 72 + mr]     = __float2bfloat16(fc[nb][1] + b0);
            st[nl * 72 + mr + 8]       = __float2bfloat16(fc[nb][2] + b1);
            st[(nl + 1) * 72 + mr + 8] = __float2bfloat16(fc[nb][3] + b1);
        }
        __syncthreads();
        const int jl = wid * 16 + (lane >> 2);
        const int gb = blockIdx.x * 8 + wid;
#pragma unroll
        for (int ks = 0; ks < 4; ks++) {
            int m = ks * 16 + 2 * (lane & 3);
            uint32_t q00 = *(uint32_t*)&st[jl * 72 + m];
            uint32_t q01 = *(uint32_t*)&st[jl * 72 + m + 8];
            uint32_t q10 = *(uint32_t*)&st[(jl + 8) * 72 + m];
            uint32_t q11 = *(uint32_t*)&st[(jl + 8) * 72 + m + 8];
            size_t fi = (((size_t)b * 256 + gb) * 4 + ks) * 32 + lane;
            if (rg == 0)
                g_Qf[fi] = make_uint4(q00, q10, q01, q11);
            else
                g_Kf[fi] = make_uint4(q00, q01, q10, q11);
        }
    }
}

// =================================================================
// Kernel 2: flash attention, warp-owned staging, 64q x 64d warps.
// CTA = 4 warps = 4 d-quarters (dh). CTA tile 64q x 256d; warp
// 64q (4 q-sets, all frags in registers) x 64d. Each warp cp.asyncs
// ITS OWN K quarter (jb = dh) and V d-slice; visibility = per-lane
// wait + syncwarp. Only cross-warp exchange is P (parity double-
// buffered) -> ONE __syncthreads per jt. Vh0/K double-buffered,
// Vh1 single-buffered. smem 83 KB, <=256 regs -> 2 CTAs/SM.
// =================================================================
// u4-layout: per-warp region (1024 u4): K[2][128] @0, Vh0[2][256] @256,
//            Vh1[256] @768. Then P[2 parity][4qs][4jb][32] @4096, LP @5120.
#define W_U4    1024
#define PB_U4   4096
#define LP_U4   5120
#define SMEM_U4 5184
#define SMEM_BYTES (SMEM_U4 * 16)   // 82944

__global__ __launch_bounds__(128) void attn_mma(
    const float* __restrict__ x, const float* __restrict__ gamma,
    float* __restrict__ out)
{
    extern __shared__ __align__(16) uint4 sbuf[];
    const uint32_t smb = smem_u32(sbuf);
    const int tid  = threadIdx.x;
    const int lane = tid & 31, dh = tid >> 5;
    const int b  = blockIdx.z;
    const int bx = blockIdx.x, by = blockIdx.y;

    // persistent Q A-fragments: 4 q-sets x 4 ks (64 regs)
    uint4 q4[4][4];
#pragma unroll
    for (int qs = 0; qs < 4; qs++) {
        int qb = bx * 4 + qs;
#pragma unroll
        for (int ks = 0; ks < 4; ks++)
            q4[qs][ks] = g_Qf[(((size_t)b * 256 + qb) * 4 + ks) * 32 + lane];
    }

    float facc[4][8][4];
#pragma unroll
    for (int qs = 0; qs < 4; qs++)
#pragma unroll
        for (int nb = 0; nb < 8; nb++)
#pragma unroll
            for (int e = 0; e < 4; e++) facc[qs][nb][e] = 0.f;
    float lr[4][2];
#pragma unroll
    for (int qs = 0; qs < 4; qs++) { lr[qs][0] = 0.f; lr[qs][1] = 0.f; }

    const uint4* Ksrc = &g_Kf[(size_t)b * 256 * 4 * 32];                 // + jt*512
    const uint4* Vsrc = &g_Vf[((size_t)b * 32 + by * 16 + dh * 4) * 256 * 32]; // warp d-slice
    const uint32_t wbase = smb + dh * (W_U4 * 16);
    uint4* const wreg = sbuf + dh * W_U4;

    // ---- prologue: G1(0) = K(0) quarter + Vh0(0) slice ----
#pragma unroll
    for (int ks = 0; ks < 4; ks++)
        cp16(wbase + (ks * 32 + lane) * 16, Ksrc + (size_t)(dh * 4 + ks) * 32 + lane);
#pragma unroll
    for (int u = 0; u < 8; u++) {
        int db = u >> 1, jb = u & 1;
        cp16(wbase + (256 + (db * 2 + jb) * 32 + lane) * 16,
             Vsrc + (size_t)db * 8192 + jb * 32 + lane);
    }
    CP_COMMIT();

    for (int jt = 0; jt < 64; jt++) {
        const int cur = jt & 1, nxt = cur ^ 1;

        // ---- G2(jt): own Vh1 slice (jb 2,3); buffer freed by own PV(jt-1) ----
#pragma unroll
        for (int u = 0; u < 8; u++) {
            int db = u >> 1, jb2 = u & 1;
            cp16(wbase + (768 + (db * 2 + jb2) * 32 + lane) * 16,
                 Vsrc + (size_t)db * 8192 + (size_t)jt * 128 + (2 + jb2) * 32 + lane);
        }
        CP_COMMIT();

        // ---- G1(jt+1): own K quarter + Vh0 slice into alt buffers ----
        if (jt < 63) {
#pragma unroll
            for (int ks = 0; ks < 4; ks++)
                cp16(wbase + (nxt * 128 + ks * 32 + lane) * 16,
                     Ksrc + (size_t)(jt + 1) * 512 + (dh * 4 + ks) * 32 + lane);
#pragma unroll
            for (int u = 0; u < 8; u++) {
                int db = u >> 1, jb = u & 1;
                cp16(wbase + (256 + nxt * 256 + (db * 2 + jb) * 32 + lane) * 16,
                     Vsrc + (size_t)db * 8192 + (size_t)(jt + 1) * 128 + jb * 32 + lane);
            }
            CP_COMMIT();
            CP_WAIT2();      // retires G1(jt): own K(jt)+Vh0(jt) landed
        } else {
            CP_WAIT1();      // retires G1(63), leaves G2(63)
        }
        __syncwarp();

        // ---- scores: own j-quarter (jb = dh), 4 q-sets ----
        const uint4* kq = wreg + cur * 128;
        uint4* Pm = sbuf + PB_U4 + cur * 512;
#pragma unroll
        for (int qs = 0; qs < 4; qs++) {
            float s0[4] = {0.f, 0.f, 0.f, 0.f};
            float s1[4] = {0.f, 0.f, 0.f, 0.f};
#pragma unroll
            for (int ks = 0; ks < 4; ks++) {
                uint4 kf = kq[ks * 32 + lane];
                mma16816(s0, (const uint32_t*)&q4[qs][ks], kf.x, kf.y);
                mma16816(s1, (const uint32_t*)&q4[qs][ks], kf.z, kf.w);
            }
            float e0 = __expf(s0[0]), e1 = __expf(s0[1]);
            float e2 = __expf(s0[2]), e3 = __expf(s0[3]);
            float f0 = __expf(s1[0]), f1 = __expf(s1[1]);
            float f2 = __expf(s1[2]), f3 = __expf(s1[3]);
            lr[qs][0] += (e0 + e1) + (f0 + f1);
            lr[qs][1] += (e2 + e3) + (f2 + f3);
            uint4 pf;
            pf.x = bpack(e0, e1);   // (q,   j-lo)
            pf.y = bpack(e2, e3);   // (q+8, j-lo)
            pf.z = bpack(f0, f1);   // (q,   j-hi)
            pf.w = bpack(f2, f3);   // (q+8, j-hi)
            Pm[(qs * 4 + dh) * 32 + lane] = pf;
        }
        __syncthreads();   // the ONE barrier: P(jt) visible to all warps

        // ---- PV half0: jb 0,1 from own Vh0(jt) ----
        const uint4* v0 = wreg + 256 + cur * 256;
#pragma unroll
        for (int jb = 0; jb < 2; jb++) {
            uint4 p[4];
#pragma unroll
            for (int qs = 0; qs < 4; qs++) p[qs] = Pm[(qs * 4 + jb) * 32 + lane];
#pragma unroll
            for (int dbl = 0; dbl < 4; dbl++) {
                uint4 vf = v0[(dbl * 2 + jb) * 32 + lane];
#pragma unroll
                for (int qs = 0; qs < 4; qs++) {
                    mma16816(facc[qs][2 * dbl],     (const uint32_t*)&p[qs], vf.x, vf.y);
                    mma16816(facc[qs][2 * dbl + 1], (const uint32_t*)&p[qs], vf.z, vf.w);
                }
            }
        }

        // ---- wait own Vh1(jt), then PV half1: jb 2,3 ----
        if (jt < 63) CP_WAIT1(); else CP_WAIT0();
        __syncwarp();
        const uint4* v1 = wreg + 768;
#pragma unroll
        for (int jb = 2; jb < 4; jb++) {
            uint4 p[4];
#pragma unroll
            for (int qs = 0; qs < 4; qs++) p[qs] = Pm[(qs * 4 + jb) * 32 + lane];
#pragma unroll
            for (int dbl = 0; dbl < 4; dbl++) {
                uint4 vf = v1[(dbl * 2 + (jb - 2)) * 32 + lane];
#pragma unroll
                for (int qs = 0; qs < 4; qs++) {
                    mma16816(facc[qs][2 * dbl],     (const uint32_t*)&p[qs], vf.x, vf.y);
                    mma16816(facc[qs][2 * dbl + 1], (const uint32_t*)&p[qs], vf.z, vf.w);
                }
            }
        }
    }

    // ---- l sums: reduce 4 lanes/row, then across dh warps via smem ----
    float* lp = (float*)(sbuf + LP_U4);   // [dh][64 q rows]
#pragma unroll
    for (int qs = 0; qs < 4; qs++) {
        lr[qs][0] += __shfl_xor_sync(0xffffffffu, lr[qs][0], 1);
        lr[qs][0] += __shfl_xor_sync(0xffffffffu, lr[qs][0], 2);
        lr[qs][1] += __shfl_xor_sync(0xffffffffu, lr[qs][1], 1);
        lr[qs][1] += __shfl_xor_sync(0xffffffffu, lr[qs][1], 2);
    }
    const int r = lane >> 2;
    if ((lane & 3) == 0) {
#pragma unroll
        for (int qs = 0; qs < 4; qs++) {
            int rowl = qs * 16 + r;
            lp[dh * 64 + rowl]     = lr[qs][0];
            lp[dh * 64 + rowl + 8] = lr[qs][1];
        }
    }
    __syncthreads();

    const float g = gamma[0];
#pragma unroll
    for (int qs = 0; qs < 4; qs++) {
        int rowl = qs * 16 + r;
        float lA = lp[rowl]     + lp[64 + rowl]     + lp[128 + rowl]     + lp[192 + rowl];
        float lB = lp[rowl + 8] + lp[64 + rowl + 8] + lp[128 + rowl + 8] + lp[192 + rowl + 8];
        float scA = g / lA, scB = g / lB;
        int q0 = bx * 64 + rowl;
#pragma unroll
        for (int dbl = 0; dbl < 4; dbl++)
#pragma unroll
            for (int nh = 0; nh < 2; nh++) {
                int d = by * 256 + dh * 64 + dbl * 16 + nh * 8 + 2 * (lane & 3);
                size_t ga = (size_t)(b * CH + d) * NPIX + q0;
                const float* fa = facc[qs][2 * dbl + nh];
                out[ga]            = fa[0] * scA + x[ga];
                out[ga + NPIX]     = fa[1] * scA + x[ga + NPIX];
                out[ga + 8]        = fa[2] * scB + x[ga + 8];
                out[ga + NPIX + 8] = fa[3] * scB + x[ga + NPIX + 8];
            }
    }
}

// =================================================================
extern "C" void kernel_launch(void* const* d_in, const int* in_sizes, int n_in,
                              void* d_out, int out_size)
{
    const float* x     = (const float*)d_in[0];
    const float* Wq    = (const float*)d_in[1];
    const float* bq    = (const float*)d_in[2];
    const float* Wk    = (const float*)d_in[3];
    const float* bk    = (const float*)d_in[4];
    const float* Wv    = (const float*)d_in[5];
    const float* bv    = (const float*)d_in[6];
    const float* gamma = (const float*)d_in[7];
    float* out = (float*)d_out;

    cudaFuncSetAttribute(attn_mma, cudaFuncAttributeMaxDynamicSharedMemorySize, SMEM_BYTES);

    conv_x_kernel<<<(BATCH * CH * NPIX) / (256 * 8), 256>>>(x);
    conv_w_kernel<<<160, 256>>>(Wq, bq, Wk, bk, Wv, bv);
    proj_mma_kernel<<<dim3(NPIX / 128, 10, BATCH), 256>>>();
    attn_mma<<<dim3(NPIX / 64, 2, BATCH), 128, SMEM_BYTES>>>(x, gamma, out);
}

// round 16
// speedup vs baseline: 1.1575x; 1.1575x over previous
#include <cuda_runtime.h>
#include <cuda_bf16.h>
#include <cstdint>

#define BATCH 4
#define CH    512
#define NPIX  4096
#define MID   64

// ---------------- global scratch ----------------
// Fragment-packed operands: one uint4 per lane per fragment.
__device__ uint4 g_Qf[BATCH * 256 * 4 * 32];        // (b, qb16, ks4, lane)  A-frag
__device__ uint4 g_Kf[BATCH * 256 * 4 * 32];        // (b, jb16, ks4, lane)  B-frag
__device__ uint4 g_Vf[BATCH * 32 * 256 * 32];       // (b, db16, kb16, lane) B-frag
__device__ __nv_bfloat16 g_xb[BATCH * CH * NPIX];   // bf16 copy of x
__device__ __nv_bfloat16 g_Wb[640 * CH];            // rows: 0-63 Wq, 64-127 Wk, 128-639 Wv
__device__ float         g_bias[640];

// ---------------- helpers ----------------
__device__ __forceinline__ uint32_t smem_u32(const void* p) {
    uint32_t a;
    asm("{ .reg .u64 t; cvta.to.shared.u64 t, %1; cvt.u32.u64 %0, t; }" : "=r"(a) : "l"(p));
    return a;
}
__device__ __forceinline__ void ldm_x4(uint32_t r[4], uint32_t addr) {
    asm volatile("ldmatrix.sync.aligned.m8n8.x4.shared.b16 {%0,%1,%2,%3}, [%4];"
                 : "=r"(r[0]), "=r"(r[1]), "=r"(r[2]), "=r"(r[3]) : "r"(addr));
}
__device__ __forceinline__ void ldm_x4t(uint32_t r[4], uint32_t addr) {
    asm volatile("ldmatrix.sync.aligned.m8n8.x4.trans.shared.b16 {%0,%1,%2,%3}, [%4];"
                 : "=r"(r[0]), "=r"(r[1]), "=r"(r[2]), "=r"(r[3]) : "r"(addr));
}
__device__ __forceinline__ void mma16816(float* c, const uint32_t* a, uint32_t b0, uint32_t b1) {
    asm volatile("mma.sync.aligned.m16n8k16.row.col.f32.bf16.bf16.f32 "
                 "{%0,%1,%2,%3}, {%4,%5,%6,%7}, {%8,%9}, {%0,%1,%2,%3};"
                 : "+f"(c[0]), "+f"(c[1]), "+f"(c[2]), "+f"(c[3])
                 : "r"(a[0]), "r"(a[1]), "r"(a[2]), "r"(a[3]), "r"(b0), "r"(b1));
}
__device__ __forceinline__ uint32_t bpack(float a, float b) {
    __nv_bfloat162 h = __floats2bfloat162_rn(a, b);
    return *(uint32_t*)&h;
}
__device__ __forceinline__ void cp16(uint32_t dst, const void* src) {
    asm volatile("cp.async.cg.shared.global [%0], [%1], 16;" :: "r"(dst), "l"(src));
}
#define CP_COMMIT() asm volatile("cp.async.commit_group;" ::: "memory")
#define CP_WAIT0()  asm volatile("cp.async.wait_group 0;" ::: "memory")
#define CP_WAIT1()  asm volatile("cp.async.wait_group 1;" ::: "memory")
#define CP_WAIT2()  asm volatile("cp.async.wait_group 2;" ::: "memory")

// =================================================================
// Kernel 0a: convert x -> bf16 (8 elems / thread)
// =================================================================
__global__ __launch_bounds__(256) void conv_x_kernel(const float* __restrict__ x)
{
    size_t i = ((size_t)blockIdx.x * 256 + threadIdx.x) * 8;
    float4 a = *(const float4*)&x[i];
    float4 c = *(const float4*)&x[i + 4];
    *(uint4*)&g_xb[i] = make_uint4(bpack(a.x, a.y), bpack(a.z, a.w),
                                   bpack(c.x, c.y), bpack(c.z, c.w));
}

// =================================================================
// Kernel 0b: pack W -> g_Wb (bf16) + g_bias
// =================================================================
__global__ __launch_bounds__(256) void conv_w_kernel(
    const float* __restrict__ Wq, const float* __restrict__ bq,
    const float* __restrict__ Wk, const float* __restrict__ bk,
    const float* __restrict__ Wv, const float* __restrict__ bv)
{
    int gid = blockIdx.x * 256 + threadIdx.x;
    size_t base = (size_t)gid * 8;
    int row = (int)(base >> 9), k = (int)(base & 511);
    const float* src;
    if (row < 64)       src = Wq + row * CH + k;
    else if (row < 128) src = Wk + (row - 64) * CH + k;
    else                src = Wv + (row - 128) * CH + k;
    float4 a = *(const float4*)src;
    float4 c = *(const float4*)(src + 4);
    *(uint4*)&g_Wb[base] = make_uint4(bpack(a.x, a.y), bpack(a.z, a.w),
                                      bpack(c.x, c.y), bpack(c.z, c.w));
    if (gid < 640)
        g_bias[gid] = (gid < 64) ? bq[gid] : (gid < 128) ? bk[gid - 64] : bv[gid - 128];
}

// =================================================================
// Kernel 1: QKV projection (bf16 mma.sync GEMM), epilogue writes
// fragment-packed Q/K/V directly.  (unchanged — verified)
// =================================================================
#define PW_STR 144
#define PX_STR 272

__global__ __launch_bounds__(256) void proj_mma_kernel()
{
    __shared__ __align__(16) char ps[9216 + 17408];
    char* Wt = ps;
    char* Xt = ps + 9216;
    const uint32_t smb = smem_u32(ps);
    const int tid = threadIdx.x, lane = tid & 31, wid = tid >> 5;
    const int mg = wid >> 1, nh = wid & 1;
    const int n0 = blockIdx.x * 128;
    const int rg = blockIdx.y;          // 0=Q rows, 1=K rows, 2-9=V rows
    const int b  = blockIdx.z;

    float fc[8][4];
#pragma unroll
    for (int nb = 0; nb < 8; nb++)
#pragma unroll
        for (int e = 0; e < 4; e++) fc[nb][e] = 0.f;

    const uint32_t aoffA  = (lane & 15) * PW_STR + (lane >> 4) * 16;
    const uint32_t aoffBT = ((lane & 7) + ((lane >> 3) & 1) * 8) * PX_STR + (lane >> 4) * 16;

    for (int kc = 0; kc < CH; kc += 64) {
        __syncthreads();
        for (int idx = tid; idx < 512; idx += 256) {
            int row = idx >> 3, c16 = idx & 7;
            *(uint4*)(Wt + row * PW_STR + c16 * 16) =
                *(const uint4*)&g_Wb[(size_t)(rg * 64 + row) * CH + kc + c16 * 8];
        }
        for (int idx = tid; idx < 1024; idx += 256) {
            int row = idx >> 4, c16 = idx & 15;
            *(uint4*)(Xt + row * PX_STR + c16 * 16) =
                *(const uint4*)&g_xb[((size_t)b * CH + kc + row) * NPIX + n0 + c16 * 8];
        }
        __syncthreads();
#pragma unroll
        for (int ks = 0; ks < 4; ks++) {
            uint32_t aW[4];
            ldm_x4(aW, smb + (mg * 16) * PW_STR + ks * 32 + aoffA);
#pragma unroll
            for (int nb = 0; nb < 4; nb++) {
                uint32_t bx[4];
                ldm_x4t(bx, smb + 9216 + (ks * 16) * PX_STR + (nh * 64 + nb * 16) * 2 + aoffBT);
                mma16816(fc[2 * nb],     aW, bx[0], bx[1]);
                mma16816(fc[2 * nb + 1], aW, bx[2], bx[3]);
            }
        }
    }

    const int mr = mg * 16 + (lane >> 2);
    const float b0 = g_bias[rg * 64 + mr], b1 = g_bias[rg * 64 + mr + 8];

    if (rg >= 2) {
        const int db = (rg - 2) * 4 + mg;
#pragma unroll
        for (int jg = 0; jg < 4; jg++) {
            int nb0 = 2 * jg, nb1 = 2 * jg + 1;
            uint4 v;
            v.x = bpack(fc[nb0][0] + b0, fc[nb0][1] + b0);
            v.y = bpack(fc[nb1][0] + b0, fc[nb1][1] + b0);
            v.z = bpack(fc[nb0][2] + b1, fc[nb0][3] + b1);
            v.w = bpack(fc[nb1][2] + b1, fc[nb1][3] + b1);
            int kb = blockIdx.x * 8 + nh * 4 + jg;
            g_Vf[(((size_t)b * 32 + db) * 256 + kb) * 32 + lane] = v;
        }
    } else {
        __syncthreads();
        __nv_bfloat16* st = (__nv_bfloat16*)ps;
#pragma unroll
        for (int nb = 0; nb < 8; nb++) {
            int nl = nh * 64 + nb * 8 + (lane & 3) * 2;
            st[nl * 72 + mr]           = __float2bfloat16(fc[nb][0] + b0);
            st[(nl + 1) * 72 + mr]     = __float2bfloat16(fc[nb][1] + b0);
            st[nl * 72 + mr + 8]       = __float2bfloat16(fc[nb][2] + b1);
            st[(nl + 1) * 72 + mr + 8] = __float2bfloat16(fc[nb][3] + b1);
        }
        __syncthreads();
        const int jl = wid * 16 + (lane >> 2);
        const int gb = blockIdx.x * 8 + wid;
#pragma unroll
        for (int ks = 0; ks < 4; ks++) {
            int m = ks * 16 + 2 * (lane & 3);
            uint32_t q00 = *(uint32_t*)&st[jl * 72 + m];
            uint32_t q01 = *(uint32_t*)&st[jl * 72 + m + 8];
            uint32_t q10 = *(uint32_t*)&st[(jl + 8) * 72 + m];
            uint32_t q11 = *(uint32_t*)&st[(jl + 8) * 72 + m + 8];
            size_t fi = (((size_t)b * 256 + gb) * 4 + ks) * 32 + lane;
            if (rg == 0)
                g_Qf[fi] = make_uint4(q00, q10, q01, q11);
            else
                g_Kf[fi] = make_uint4(q00, q01, q10, q11);
        }
    }
}

// =================================================================
// Kernel 2: flash attention, warp-owned staging (R14 mainloop).
// CTA = 4 warps = 4 d-quarters (dh). CTA tile 32q x 256d; warp
// 32q (2 q-sets) x 64d. Each warp cp.asyncs ITS OWN K quarter
// (jb = dh) and V d-slice; visibility = per-lane wait + syncwarp.
// Only cross-warp exchange is P (parity double-buffered) ->
// ONE __syncthreads per jt. Vh0/K double-buffered, Vh1 single-
// buffered. 3 CTAs/SM (pinned). NEW: coalesced float4 epilogue via
// per-warp smem staging (stride-36 = conflict-free both directions).
// =================================================================
// u4-layout: per-warp region (1024 u4): K[2][128] @0, Vh0[2][256] @256,
//            Vh1[256] @768. Then P[2][2qs][4jb][32] @4096, LP @4608.
#define W_U4    1024
#define PB_U4   4096
#define LP_U4   4608
#define SMEM_U4 4640
#define SMEM_BYTES (SMEM_U4 * 16)   // 74240

__global__ __launch_bounds__(128, 3) void attn_mma(
    const float* __restrict__ x, const float* __restrict__ gamma,
    float* __restrict__ out)
{
    extern __shared__ __align__(16) uint4 sbuf[];
    const uint32_t smb = smem_u32(sbuf);
    const int tid  = threadIdx.x;
    const int lane = tid & 31, dh = tid >> 5;
    const int b  = blockIdx.z;
    const int bx = blockIdx.x, by = blockIdx.y;

    // persistent Q A-fragments: 2 q-sets x 4 ks
    uint4 q4[2][4];
#pragma unroll
    for (int qs = 0; qs < 2; qs++) {
        int qb = bx * 2 + qs;
#pragma unroll
        for (int ks = 0; ks < 4; ks++)
            q4[qs][ks] = g_Qf[(((size_t)b * 256 + qb) * 4 + ks) * 32 + lane];
    }

    float facc[2][8][4];
#pragma unroll
    for (int qs = 0; qs < 2; qs++)
#pragma unroll
        for (int nb = 0; nb < 8; nb++)
#pragma unroll
            for (int e = 0; e < 4; e++) facc[qs][nb][e] = 0.f;
    float lr[2][2] = {{0.f, 0.f}, {0.f, 0.f}};

    const uint4* Ksrc = &g_Kf[(size_t)b * 256 * 4 * 32];                 // + jt*512
    const uint4* Vsrc = &g_Vf[((size_t)b * 32 + by * 16 + dh * 4) * 256 * 32]; // warp d-slice
    const uint32_t wbase = smb + dh * (W_U4 * 16);
    uint4* const wreg = sbuf + dh * W_U4;

    // ---- prologue: G1(0) = K(0) quarter + Vh0(0) slice ----
#pragma unroll
    for (int ks = 0; ks < 4; ks++)
        cp16(wbase + (ks * 32 + lane) * 16, Ksrc + (size_t)(dh * 4 + ks) * 32 + lane);
#pragma unroll
    for (int u = 0; u < 8; u++) {
        int db = u >> 1, jb = u & 1;
        cp16(wbase + (256 + (db * 2 + jb) * 32 + lane) * 16,
             Vsrc + (size_t)db * 8192 + jb * 32 + lane);
    }
    CP_COMMIT();

    for (int jt = 0; jt < 64; jt++) {
        const int cur = jt & 1, nxt = cur ^ 1;

        // ---- G2(jt): own Vh1 slice (jb 2,3); buffer freed by own PV(jt-1) ----
#pragma unroll
        for (int u = 0; u < 8; u++) {
            int db = u >> 1, jb2 = u & 1;
            cp16(wbase + (768 + (db * 2 + jb2) * 32 + lane) * 16,
                 Vsrc + (size_t)db * 8192 + (size_t)jt * 128 + (2 + jb2) * 32 + lane);
        }
        CP_COMMIT();

        // ---- G1(jt+1): own K quarter + Vh0 slice into alt buffers ----
        if (jt < 63) {
#pragma unroll
            for (int ks = 0; ks < 4; ks++)
                cp16(wbase + (nxt * 128 + ks * 32 + lane) * 16,
                     Ksrc + (size_t)(jt + 1) * 512 + (dh * 4 + ks) * 32 + lane);
#pragma unroll
            for (int u = 0; u < 8; u++) {
                int db = u >> 1, jb = u & 1;
                cp16(wbase + (256 + nxt * 256 + (db * 2 + jb) * 32 + lane) * 16,
                     Vsrc + (size_t)db * 8192 + (size_t)(jt + 1) * 128 + jb * 32 + lane);
            }
            CP_COMMIT();
            CP_WAIT2();      // retires G1(jt): own K(jt)+Vh0(jt) landed
        } else {
            CP_WAIT1();      // retires G1(63), leaves G2(63)
        }
        __syncwarp();

        // ---- scores: own j-quarter (jb = dh), both q-sets ----
        const uint4* kq = wreg + cur * 128;
        float s[2][2][4];
#pragma unroll
        for (int qs = 0; qs < 2; qs++)
#pragma unroll
            for (int h = 0; h < 2; h++)
#pragma unroll
                for (int e = 0; e < 4; e++) s[qs][h][e] = 0.f;
#pragma unroll
        for (int ks = 0; ks < 4; ks++) {
            uint4 kf = kq[ks * 32 + lane];
            mma16816(s[0][0], (const uint32_t*)&q4[0][ks], kf.x, kf.y);
            mma16816(s[0][1], (const uint32_t*)&q4[0][ks], kf.z, kf.w);
            mma16816(s[1][0], (const uint32_t*)&q4[1][ks], kf.x, kf.y);
            mma16816(s[1][1], (const uint32_t*)&q4[1][ks], kf.z, kf.w);
        }

        // exp + P A-frag, store own quarter (parity-buffered)
        uint4* Pm = sbuf + PB_U4 + cur * 256;
#pragma unroll
        for (int qs = 0; qs < 2; qs++) {
            float e0 = __expf(s[qs][0][0]), e1 = __expf(s[qs][0][1]);
            float e2 = __expf(s[qs][0][2]), e3 = __expf(s[qs][0][3]);
            float f0 = __expf(s[qs][1][0]), f1 = __expf(s[qs][1][1]);
            float f2 = __expf(s[qs][1][2]), f3 = __expf(s[qs][1][3]);
            lr[qs][0] += (e0 + e1) + (f0 + f1);
            lr[qs][1] += (e2 + e3) + (f2 + f3);
            uint4 pf;
            pf.x = bpack(e0, e1);   // (q,   j-lo)
            pf.y = bpack(e2, e3);   // (q+8, j-lo)
            pf.z = bpack(f0, f1);   // (q,   j-hi)
            pf.w = bpack(f2, f3);   // (q+8, j-hi)
            Pm[(qs * 4 + dh) * 32 + lane] = pf;
        }
        __syncthreads();   // the ONE barrier: P(jt) visible to all warps

        // ---- PV half0: jb 0,1 from own Vh0(jt) ----
        const uint4* v0 = wreg + 256 + cur * 256;
#pragma unroll
        for (int jb = 0; jb < 2; jb++) {
            uint4 p0 = Pm[jb * 32 + lane];
            uint4 p1 = Pm[(4 + jb) * 32 + lane];
#pragma unroll
            for (int dbl = 0; dbl < 4; dbl++) {
                uint4 vf = v0[(dbl * 2 + jb) * 32 + lane];
                mma16816(facc[0][2 * dbl],     (const uint32_t*)&p0, vf.x, vf.y);
                mma16816(facc[0][2 * dbl + 1], (const uint32_t*)&p0, vf.z, vf.w);
                mma16816(facc[1][2 * dbl],     (const uint32_t*)&p1, vf.x, vf.y);
                mma16816(facc[1][2 * dbl + 1], (const uint32_t*)&p1, vf.z, vf.w);
            }
        }

        // ---- wait own Vh1(jt), then PV half1: jb 2,3 ----
        if (jt < 63) CP_WAIT1(); else CP_WAIT0();
        __syncwarp();
        const uint4* v1 = wreg + 768;
#pragma unroll
        for (int jb = 2; jb < 4; jb++) {
            uint4 p0 = Pm[jb * 32 + lane];
            uint4 p1 = Pm[(4 + jb) * 32 + lane];
#pragma unroll
            for (int dbl = 0; dbl < 4; dbl++) {
                uint4 vf = v1[(dbl * 2 + (jb - 2)) * 32 + lane];
                mma16816(facc[0][2 * dbl],     (const uint32_t*)&p0, vf.x, vf.y);
                mma16816(facc[0][2 * dbl + 1], (const uint32_t*)&p0, vf.z, vf.w);
                mma16816(facc[1][2 * dbl],     (const uint32_t*)&p1, vf.x, vf.y);
                mma16816(facc[1][2 * dbl + 1], (const uint32_t*)&p1, vf.z, vf.w);
            }
        }
    }

    // ---- l sums: reduce 4 lanes/row, then across dh warps via smem ----
    float* lp = (float*)(sbuf + LP_U4);   // [dh][32 q rows]
#pragma unroll
    for (int qs = 0; qs < 2; qs++) {
        lr[qs][0] += __shfl_xor_sync(0xffffffffu, lr[qs][0], 1);
        lr[qs][0] += __shfl_xor_sync(0xffffffffu, lr[qs][0], 2);
        lr[qs][1] += __shfl_xor_sync(0xffffffffu, lr[qs][1], 1);
        lr[qs][1] += __shfl_xor_sync(0xffffffffu, lr[qs][1], 2);
    }
    const int r = lane >> 2;
    if ((lane & 3) == 0) {
#pragma unroll
        for (int qs = 0; qs < 2; qs++) {
            int rowl = qs * 16 + r;
            lp[dh * 32 + rowl]     = lr[qs][0];
            lp[dh * 32 + rowl + 8] = lr[qs][1];
        }
    }
    __syncthreads();

    // ---- epilogue: scale, stage to per-warp smem (stride 36 floats),
    //      then fully-coalesced float4 out = feat + x ----
    const float g = gamma[0];
    float* wst = (float*)wreg;   // 64 d-rows x 36 stride = 2304 floats (<=4096)
#pragma unroll
    for (int qs = 0; qs < 2; qs++) {
        int rowl = qs * 16 + r;
        float lA = lp[rowl]     + lp[32 + rowl]     + lp[64 + rowl]     + lp[96 + rowl];
        float lB = lp[rowl + 8] + lp[32 + rowl + 8] + lp[64 + rowl + 8] + lp[96 + rowl + 8];
        float scA = g / lA, scB = g / lB;
#pragma unroll
        for (int dbl = 0; dbl < 4; dbl++)
#pragma unroll
            for (int nh = 0; nh < 2; nh++) {
                int dl = dbl * 16 + nh * 8 + 2 * (lane & 3);
                const float* fa = facc[qs][2 * dbl + nh];
                wst[dl * 36 + rowl]           = fa[0] * scA;
                wst[(dl + 1) * 36 + rowl]     = fa[1] * scA;
                wst[dl * 36 + rowl + 8]       = fa[2] * scB;
                wst[(dl + 1) * 36 + rowl + 8] = fa[3] * scB;
            }
    }
    __syncwarp();

    const int q0 = bx * 32;
#pragma unroll
    for (int k = 0; k < 16; k++) {
        int idx = k * 32 + lane;
        int row = idx >> 3, c4 = idx & 7;        // 64 d-rows x 8 float4-cols
        int d = by * 256 + dh * 64 + row;
        size_t ga = (size_t)(b * CH + d) * NPIX + q0 + c4 * 4;
        float4 xv = *(const float4*)&x[ga];
        float4 o  = *(float4*)&wst[row * 36 + c4 * 4];
        o.x += xv.x; o.y += xv.y; o.z += xv.z; o.w += xv.w;
        *(float4*)&out[ga] = o;
    }
}

// =================================================================
extern "C" void kernel_launch(void* const* d_in, const int* in_sizes, int n_in,
                              void* d_out, int out_size)
{
    const float* x     = (const float*)d_in[0];
    const float* Wq    = (const float*)d_in[1];
    const float* bq    = (const float*)d_in[2];
    const float* Wk    = (const float*)d_in[3];
    const float* bk    = (const float*)d_in[4];
    const float* Wv    = (const float*)d_in[5];
    const float* bv    = (const float*)d_in[6];
    const float* gamma = (const float*)d_in[7];
    float* out = (float*)d_out;

    cudaFuncSetAttribute(attn_mma, cudaFuncAttributeMaxDynamicSharedMemorySize, SMEM_BYTES);

    conv_x_kernel<<<(BATCH * CH * NPIX) / (256 * 8), 256>>>(x);
    conv_w_kernel<<<160, 256>>>(Wq, bq, Wk, bk, Wv, bv);
    proj_mma_kernel<<<dim3(NPIX / 128, 10, BATCH), 256>>>();
    attn_mma<<<dim3(NPIX / 32, 2, BATCH), 128, SMEM_BYTES>>>(x, gamma, out);
}

// round 17
// speedup vs baseline: 1.1988x; 1.0356x over previous
#include <cuda_runtime.h>
#include <cuda_bf16.h>
#include <cstdint>

#define BATCH 4
#define CH    512
#define NPIX  4096
#define MID   64
#define LOG2E 1.4426950408889634f

// ---------------- global scratch ----------------
// Fragment-packed operands: one uint4 per lane per fragment.
__device__ uint4 g_Qf[BATCH * 256 * 4 * 32];        // (b, qb16, ks4, lane)  A-frag (pre-scaled by log2e)
__device__ uint4 g_Kf[BATCH * 256 * 4 * 32];        // (b, jb16, ks4, lane)  B-frag
__device__ uint4 g_Vf[BATCH * 32 * 256 * 32];       // (b, db16, kb16, lane) B-frag
__device__ __nv_bfloat16 g_Wb[640 * CH];            // rows: 0-63 Wq, 64-127 Wk, 128-639 Wv
__device__ float         g_bias[640];

// ---------------- helpers ----------------
__device__ __forceinline__ uint32_t smem_u32(const void* p) {
    uint32_t a;
    asm("{ .reg .u64 t; cvta.to.shared.u64 t, %1; cvt.u32.u64 %0, t; }" : "=r"(a) : "l"(p));
    return a;
}
__device__ __forceinline__ void ldm_x4(uint32_t r[4], uint32_t addr) {
    asm volatile("ldmatrix.sync.aligned.m8n8.x4.shared.b16 {%0,%1,%2,%3}, [%4];"
                 : "=r"(r[0]), "=r"(r[1]), "=r"(r[2]), "=r"(r[3]) : "r"(addr));
}
__device__ __forceinline__ void ldm_x4t(uint32_t r[4], uint32_t addr) {
    asm volatile("ldmatrix.sync.aligned.m8n8.x4.trans.shared.b16 {%0,%1,%2,%3}, [%4];"
                 : "=r"(r[0]), "=r"(r[1]), "=r"(r[2]), "=r"(r[3]) : "r"(addr));
}
__device__ __forceinline__ void mma16816(float* c, const uint32_t* a, uint32_t b0, uint32_t b1) {
    asm volatile("mma.sync.aligned.m16n8k16.row.col.f32.bf16.bf16.f32 "
                 "{%0,%1,%2,%3}, {%4,%5,%6,%7}, {%8,%9}, {%0,%1,%2,%3};"
                 : "+f"(c[0]), "+f"(c[1]), "+f"(c[2]), "+f"(c[3])
                 : "r"(a[0]), "r"(a[1]), "r"(a[2]), "r"(a[3]), "r"(b0), "r"(b1));
}
__device__ __forceinline__ uint32_t bpack(float a, float b) {
    __nv_bfloat162 h = __floats2bfloat162_rn(a, b);
    return *(uint32_t*)&h;
}
__device__ __forceinline__ float ex2(float v) {
    float r;
    asm("ex2.approx.ftz.f32 %0, %1;" : "=f"(r) : "f"(v));
    return r;
}
__device__ __forceinline__ void cp16(uint32_t dst, const void* src) {
    asm volatile("cp.async.cg.shared.global [%0], [%1], 16;" :: "r"(dst), "l"(src));
}
#define CP_COMMIT() asm volatile("cp.async.commit_group;" ::: "memory")
#define CP_WAIT0()  asm volatile("cp.async.wait_group 0;" ::: "memory")
#define CP_WAIT1()  asm volatile("cp.async.wait_group 1;" ::: "memory")
#define CP_WAIT2()  asm volatile("cp.async.wait_group 2;" ::: "memory")

// =================================================================
// Kernel 0: pack W -> g_Wb (bf16) + g_bias
// =================================================================
__global__ __launch_bounds__(256) void conv_w_kernel(
    const float* __restrict__ Wq, const float* __restrict__ bq,
    const float* __restrict__ Wk, const float* __restrict__ bk,
    const float* __restrict__ Wv, const float* __restrict__ bv)
{
    int gid = blockIdx.x * 256 + threadIdx.x;
    size_t base = (size_t)gid * 8;
    int row = (int)(base >> 9), k = (int)(base & 511);
    const float* src;
    if (row < 64)       src = Wq + row * CH + k;
    else if (row < 128) src = Wk + (row - 64) * CH + k;
    else                src = Wv + (row - 128) * CH + k;
    float4 a = *(const float4*)src;
    float4 c = *(const float4*)(src + 4);
    *(uint4*)&g_Wb[base] = make_uint4(bpack(a.x, a.y), bpack(a.z, a.w),
                                      bpack(c.x, c.y), bpack(c.z, c.w));
    if (gid < 640)
        g_bias[gid] = (gid < 64) ? bq[gid] : (gid < 128) ? bk[gid - 64] : bv[gid - 128];
}

// =================================================================
// Kernel 1: QKV projection (bf16 mma.sync GEMM), fused x->bf16
// conversion, 2 row-groups per CTA (shared Xs staging), epilogue
// writes fragment-packed Q/K/V. Q is pre-scaled by log2(e).
// =================================================================
#define PW_STR 144
#define PX_STR 272

__global__ __launch_bounds__(256) void proj_mma_kernel(const float* __restrict__ x)
{
    __shared__ __align__(16) char ps[2 * 9216 + 17408];   // Wt0, Wt1, Xt
    char* Wt0 = ps;
    char* Wt1 = ps + 9216;
    char* Xt  = ps + 18432;
    const uint32_t smb = smem_u32(ps);
    const int tid = threadIdx.x, lane = tid & 31, wid = tid >> 5;
    const int mg = wid >> 1, nh = wid & 1;
    const int n0 = blockIdx.x * 128;
    const int rg0 = blockIdx.y * 2;     // row-group pair (rg0, rg0+1); 0=Q,1=K,2-9=V
    const int b  = blockIdx.z;

    float fc[2][8][4];
#pragma unroll
    for (int t = 0; t < 2; t++)
#pragma unroll
        for (int nb = 0; nb < 8; nb++)
#pragma unroll
            for (int e = 0; e < 4; e++) fc[t][nb][e] = 0.f;

    const uint32_t aoffA  = (lane & 15) * PW_STR + (lane >> 4) * 16;
    const uint32_t aoffBT = ((lane & 7) + ((lane >> 3) & 1) * 8) * PX_STR + (lane >> 4) * 16;

    for (int kc = 0; kc < CH; kc += 64) {
        __syncthreads();
        // stage both W tiles
        for (int idx = tid; idx < 512; idx += 256) {
            int row = idx >> 3, c16 = idx & 7;
            *(uint4*)(Wt0 + row * PW_STR + c16 * 16) =
                *(const uint4*)&g_Wb[(size_t)(rg0 * 64 + row) * CH + kc + c16 * 8];
            *(uint4*)(Wt1 + row * PW_STR + c16 * 16) =
                *(const uint4*)&g_Wb[(size_t)((rg0 + 1) * 64 + row) * CH + kc + c16 * 8];
        }
        // stage X tile: read fp32 x, convert inline (conv_x fused)
        for (int idx = tid; idx < 1024; idx += 256) {
            int row = idx >> 4, c16 = idx & 15;
            const float* xs = &x[((size_t)b * CH + kc + row) * NPIX + n0 + c16 * 8];
            float4 a = *(const float4*)xs;
            float4 c = *(const float4*)(xs + 4);
            *(uint4*)(Xt + row * PX_STR + c16 * 16) =
                make_uint4(bpack(a.x, a.y), bpack(a.z, a.w),
                           bpack(c.x, c.y), bpack(c.z, c.w));
        }
        __syncthreads();
#pragma unroll
        for (int ks = 0; ks < 4; ks++) {
            uint32_t aW0[4], aW1[4];
            ldm_x4(aW0, smb + (mg * 16) * PW_STR + ks * 32 + aoffA);
            ldm_x4(aW1, smb + 9216 + (mg * 16) * PW_STR + ks * 32 + aoffA);
#pragma unroll
            for (int nb = 0; nb < 4; nb++) {
                uint32_t bx[4];
                ldm_x4t(bx, smb + 18432 + (ks * 16) * PX_STR + (nh * 64 + nb * 16) * 2 + aoffBT);
                mma16816(fc[0][2 * nb],     aW0, bx[0], bx[1]);
                mma16816(fc[0][2 * nb + 1], aW0, bx[2], bx[3]);
                mma16816(fc[1][2 * nb],     aW1, bx[0], bx[1]);
                mma16816(fc[1][2 * nb + 1], aW1, bx[2], bx[3]);
            }
        }
    }

    const int mr = mg * 16 + (lane >> 2);

#pragma unroll
    for (int t = 0; t < 2; t++) {
        const int rg = rg0 + t;
        const float b0 = g_bias[rg * 64 + mr], b1 = g_bias[rg * 64 + mr + 8];
        if (rg >= 2) {
            // V fragment-packed store
            const int db = (rg - 2) * 4 + mg;
#pragma unroll
            for (int jg = 0; jg < 4; jg++) {
                int nb0 = 2 * jg, nb1 = 2 * jg + 1;
                uint4 v;
                v.x = bpack(fc[t][nb0][0] + b0, fc[t][nb0][1] + b0);
                v.y = bpack(fc[t][nb1][0] + b0, fc[t][nb1][1] + b0);
                v.z = bpack(fc[t][nb0][2] + b1, fc[t][nb0][3] + b1);
                v.w = bpack(fc[t][nb1][2] + b1, fc[t][nb1][3] + b1);
                int kb = blockIdx.x * 8 + nh * 4 + jg;
                g_Vf[(((size_t)b * 32 + db) * 256 + kb) * 32 + lane] = v;
            }
        } else {
            // Q/K: transpose through smem st[128 n][72 m], then gather frags.
            // Q (rg==0) is pre-scaled by log2e so attn can use raw ex2.
            const float sc = (rg == 0) ? LOG2E : 1.0f;
            __syncthreads();
            __nv_bfloat16* st = (__nv_bfloat16*)ps;
#pragma unroll
            for (int nb = 0; nb < 8; nb++) {
                int nl = nh * 64 + nb * 8 + (lane & 3) * 2;
                st[nl * 72 + mr]           = __float2bfloat16((fc[t][nb][0] + b0) * sc);
                st[(nl + 1) * 72 + mr]     = __float2bfloat16((fc[t][nb][1] + b0) * sc);
                st[nl * 72 + mr + 8]       = __float2bfloat16((fc[t][nb][2] + b1) * sc);
                st[(nl + 1) * 72 + mr + 8] = __float2bfloat16((fc[t][nb][3] + b1) * sc);
            }
            __syncthreads();
            const int jl = wid * 16 + (lane >> 2);
            const int gb = blockIdx.x * 8 + wid;
#pragma unroll
            for (int ks = 0; ks < 4; ks++) {
                int m = ks * 16 + 2 * (lane & 3);
                uint32_t q00 = *(uint32_t*)&st[jl * 72 + m];
                uint32_t q01 = *(uint32_t*)&st[jl * 72 + m + 8];
                uint32_t q10 = *(uint32_t*)&st[(jl + 8) * 72 + m];
                uint32_t q11 = *(uint32_t*)&st[(jl + 8) * 72 + m + 8];
                size_t fi = (((size_t)b * 256 + gb) * 4 + ks) * 32 + lane;
                if (rg == 0)
                    g_Qf[fi] = make_uint4(q00, q10, q01, q11);   // A-frag order
                else
                    g_Kf[fi] = make_uint4(q00, q01, q10, q11);   // B-frag order
            }
        }
    }
}

// =================================================================
// Kernel 2: flash attention, warp-owned staging (R14/R16 mainloop).
// CTA = 4 warps = 4 d-quarters (dh). CTA tile 32q x 256d; warp
// 32q (2 q-sets) x 64d. Each warp cp.asyncs ITS OWN K quarter
// (jb = dh) and V d-slice; visibility = per-lane wait + syncwarp.
// Only cross-warp exchange is P (parity double-buffered) ->
// ONE __syncthreads per jt. Vh0/K double-buffered, Vh1 single-
// buffered. 3 CTAs/SM (pinned). Coalesced float4 epilogue via
// per-warp smem staging. exp = raw ex2 (Q pre-scaled by log2e).
// =================================================================
// u4-layout: per-warp region (1024 u4): K[2][128] @0, Vh0[2][256] @256,
//            Vh1[256] @768. Then P[2][2qs][4jb][32] @4096, LP @4608.
#define W_U4    1024
#define PB_U4   4096
#define LP_U4   4608
#define SMEM_U4 4640
#define SMEM_BYTES (SMEM_U4 * 16)   // 74240

__global__ __launch_bounds__(128, 3) void attn_mma(
    const float* __restrict__ x, const float* __restrict__ gamma,
    float* __restrict__ out)
{
    extern __shared__ __align__(16) uint4 sbuf[];
    const uint32_t smb = smem_u32(sbuf);
    const int tid  = threadIdx.x;
    const int lane = tid & 31, dh = tid >> 5;
    const int b  = blockIdx.z;
    const int bx = blockIdx.x, by = blockIdx.y;

    // persistent Q A-fragments: 2 q-sets x 4 ks
    uint4 q4[2][4];
#pragma unroll
    for (int qs = 0; qs < 2; qs++) {
        int qb = bx * 2 + qs;
#pragma unroll
        for (int ks = 0; ks < 4; ks++)
            q4[qs][ks] = g_Qf[(((size_t)b * 256 + qb) * 4 + ks) * 32 + lane];
    }

    float facc[2][8][4];
#pragma unroll
    for (int qs = 0; qs < 2; qs++)
#pragma unroll
        for (int nb = 0; nb < 8; nb++)
#pragma unroll
            for (int e = 0; e < 4; e++) facc[qs][nb][e] = 0.f;
    float lr[2][2] = {{0.f, 0.f}, {0.f, 0.f}};

    const uint4* Ksrc = &g_Kf[(size_t)b * 256 * 4 * 32];                 // + jt*512
    const uint4* Vsrc = &g_Vf[((size_t)b * 32 + by * 16 + dh * 4) * 256 * 32]; // warp d-slice
    const uint32_t wbase = smb + dh * (W_U4 * 16);
    uint4* const wreg = sbuf + dh * W_U4;

    // ---- prologue: G1(0) = K(0) quarter + Vh0(0) slice ----
#pragma unroll
    for (int ks = 0; ks < 4; ks++)
        cp16(wbase + (ks * 32 + lane) * 16, Ksrc + (size_t)(dh * 4 + ks) * 32 + lane);
#pragma unroll
    for (int u = 0; u < 8; u++) {
        int db = u >> 1, jb = u & 1;
        cp16(wbase + (256 + (db * 2 + jb) * 32 + lane) * 16,
             Vsrc + (size_t)db * 8192 + jb * 32 + lane);
    }
    CP_COMMIT();

    for (int jt = 0; jt < 64; jt++) {
        const int cur = jt & 1, nxt = cur ^ 1;

        // ---- G2(jt): own Vh1 slice (jb 2,3); buffer freed by own PV(jt-1) ----
#pragma unroll
        for (int u = 0; u < 8; u++) {
            int db = u >> 1, jb2 = u & 1;
            cp16(wbase + (768 + (db * 2 + jb2) * 32 + lane) * 16,
                 Vsrc + (size_t)db * 8192 + (size_t)jt * 128 + (2 + jb2) * 32 + lane);
        }
        CP_COMMIT();

        // ---- G1(jt+1): own K quarter + Vh0 slice into alt buffers ----
        if (jt < 63) {
#pragma unroll
            for (int ks = 0; ks < 4; ks++)
                cp16(wbase + (nxt * 128 + ks * 32 + lane) * 16,
                     Ksrc + (size_t)(jt + 1) * 512 + (dh * 4 + ks) * 32 + lane);
#pragma unroll
            for (int u = 0; u < 8; u++) {
                int db = u >> 1, jb = u & 1;
                cp16(wbase + (256 + nxt * 256 + (db * 2 + jb) * 32 + lane) * 16,
                     Vsrc + (size_t)db * 8192 + (size_t)(jt + 1) * 128 + jb * 32 + lane);
            }
            CP_COMMIT();
            CP_WAIT2();      // retires G1(jt): own K(jt)+Vh0(jt) landed
        } else {
            CP_WAIT1();      // retires G1(63), leaves G2(63)
        }
        __syncwarp();

        // ---- scores: own j-quarter (jb = dh), both q-sets ----
        const uint4* kq = wreg + cur * 128;
        float s[2][2][4];
#pragma unroll
        for (int qs = 0; qs < 2; qs++)
#pragma unroll
            for (int h = 0; h < 2; h++)
#pragma unroll
                for (int e = 0; e < 4; e++) s[qs][h][e] = 0.f;
#pragma unroll
        for (int ks = 0; ks < 4; ks++) {
            uint4 kf = kq[ks * 32 + lane];
            mma16816(s[0][0], (const uint32_t*)&q4[0][ks], kf.x, kf.y);
            mma16816(s[0][1], (const uint32_t*)&q4[0][ks], kf.z, kf.w);
            mma16816(s[1][0], (const uint32_t*)&q4[1][ks], kf.x, kf.y);
            mma16816(s[1][1], (const uint32_t*)&q4[1][ks], kf.z, kf.w);
        }

        // ex2 + P A-frag, store own quarter (parity-buffered).
        // Q was pre-scaled by log2e, so ex2(s) == exp(score).
        uint4* Pm = sbuf + PB_U4 + cur * 256;
#pragma unroll
        for (int qs = 0; qs < 2; qs++) {
            float e0 = ex2(s[qs][0][0]), e1 = ex2(s[qs][0][1]);
            float e2 = ex2(s[qs][0][2]), e3 = ex2(s[qs][0][3]);
            float f0 = ex2(s[qs][1][0]), f1 = ex2(s[qs][1][1]);
            float f2 = ex2(s[qs][1][2]), f3 = ex2(s[qs][1][3]);
            lr[qs][0] += (e0 + e1) + (f0 + f1);
            lr[qs][1] += (e2 + e3) + (f2 + f3);
            uint4 pf;
            pf.x = bpack(e0, e1);   // (q,   j-lo)
            pf.y = bpack(e2, e3);   // (q+8, j-lo)
            pf.z = bpack(f0, f1);   // (q,   j-hi)
            pf.w = bpack(f2, f3);   // (q+8, j-hi)
            Pm[(qs * 4 + dh) * 32 + lane] = pf;
        }
        __syncthreads();   // the ONE barrier: P(jt) visible to all warps

        // ---- PV half0: jb 0,1 from own Vh0(jt) ----
        const uint4* v0 = wreg + 256 + cur * 256;
#pragma unroll
        for (int jb = 0; jb < 2; jb++) {
            uint4 p0 = Pm[jb * 32 + lane];
            uint4 p1 = Pm[(4 + jb) * 32 + lane];
#pragma unroll
            for (int dbl = 0; dbl < 4; dbl++) {
                uint4 vf = v0[(dbl * 2 + jb) * 32 + lane];
                mma16816(facc[0][2 * dbl],     (const uint32_t*)&p0, vf.x, vf.y);
                mma16816(facc[0][2 * dbl + 1], (const uint32_t*)&p0, vf.z, vf.w);
                mma16816(facc[1][2 * dbl],     (const uint32_t*)&p1, vf.x, vf.y);
                mma16816(facc[1][2 * dbl + 1], (const uint32_t*)&p1, vf.z, vf.w);
            }
        }

        // ---- wait own Vh1(jt), then PV half1: jb 2,3 ----
        if (jt < 63) CP_WAIT1(); else CP_WAIT0();
        __syncwarp();
        const uint4* v1 = wreg + 768;
#pragma unroll
        for (int jb = 2; jb < 4; jb++) {
            uint4 p0 = Pm[jb * 32 + lane];
            uint4 p1 = Pm[(4 + jb) * 32 + lane];
#pragma unroll
            for (int dbl = 0; dbl < 4; dbl++) {
                uint4 vf = v1[(dbl * 2 + (jb - 2)) * 32 + lane];
                mma16816(facc[0][2 * dbl],     (const uint32_t*)&p0, vf.x, vf.y);
                mma16816(facc[0][2 * dbl + 1], (const uint32_t*)&p0, vf.z, vf.w);
                mma16816(facc[1][2 * dbl],     (const uint32_t*)&p1, vf.x, vf.y);
                mma16816(facc[1][2 * dbl + 1], (const uint32_t*)&p1, vf.z, vf.w);
            }
        }
    }

    // ---- l sums: reduce 4 lanes/row, then across dh warps via smem ----
    float* lp = (float*)(sbuf + LP_U4);   // [dh][32 q rows]
#pragma unroll
    for (int qs = 0; qs < 2; qs++) {
        lr[qs][0] += __shfl_xor_sync(0xffffffffu, lr[qs][0], 1);
        lr[qs][0] += __shfl_xor_sync(0xffffffffu, lr[qs][0], 2);
        lr[qs][1] += __shfl_xor_sync(0xffffffffu, lr[qs][1], 1);
        lr[qs][1] += __shfl_xor_sync(0xffffffffu, lr[qs][1], 2);
    }
    const int r = lane >> 2;
    if ((lane & 3) == 0) {
#pragma unroll
        for (int qs = 0; qs < 2; qs++) {
            int rowl = qs * 16 + r;
            lp[dh * 32 + rowl]     = lr[qs][0];
            lp[dh * 32 + rowl + 8] = lr[qs][1];
        }
    }
    __syncthreads();

    // ---- epilogue: scale, stage to per-warp smem (stride 36 floats),
    //      then fully-coalesced float4 out = feat + x ----
    const float g = gamma[0];
    float* wst = (float*)wreg;   // 64 d-rows x 36 stride = 2304 floats (<=4096)
#pragma unroll
    for (int qs = 0; qs < 2; qs++) {
        int rowl = qs * 16 + r;
        float lA = lp[rowl]     + lp[32 + rowl]     + lp[64 + rowl]     + lp[96 + rowl];
        float lB = lp[rowl + 8] + lp[32 + rowl + 8] + lp[64 + rowl + 8] + lp[96 + rowl + 8];
        float scA = g / lA, scB = g / lB;
#pragma unroll
        for (int dbl = 0; dbl < 4; dbl++)
#pragma unroll
            for (int nh = 0; nh < 2; nh++) {
                int dl = dbl * 16 + nh * 8 + 2 * (lane & 3);
                const float* fa = facc[qs][2 * dbl + nh];
                wst[dl * 36 + rowl]           = fa[0] * scA;
                wst[(dl + 1) * 36 + rowl]     = fa[1] * scA;
                wst[dl * 36 + rowl + 8]       = fa[2] * scB;
                wst[(dl + 1) * 36 + rowl + 8] = fa[3] * scB;
            }
    }
    __syncwarp();

    const int q0 = bx * 32;
#pragma unroll
    for (int k = 0; k < 16; k++) {
        int idx = k * 32 + lane;
        int row = idx >> 3, c4 = idx & 7;        // 64 d-rows x 8 float4-cols
        int d = by * 256 + dh * 64 + row;
        size_t ga = (size_t)(b * CH + d) * NPIX + q0 + c4 * 4;
        float4 xv = *(const float4*)&x[ga];
        float4 o  = *(float4*)&wst[row * 36 + c4 * 4];
        o.x += xv.x; o.y += xv.y; o.z += xv.z; o.w += xv.w;
        *(float4*)&out[ga] = o;
    }
}

// =================================================================
extern "C" void kernel_launch(void* const* d_in, const int* in_sizes, int n_in,
                              void* d_out, int out_size)
{
    const float* x     = (const float*)d_in[0];
    const float* Wq    = (const float*)d_in[1];
    const float* bq    = (const float*)d_in[2];
    const float* Wk    = (const float*)d_in[3];
    const float* bk    = (const float*)d_in[4];
    const float* Wv    = (const float*)d_in[5];
    const float* bv    = (const float*)d_in[6];
    const float* gamma = (const float*)d_in[7];
    float* out = (float*)d_out;

    cudaFuncSetAttribute(attn_mma, cudaFuncAttributeMaxDynamicSharedMemorySize, SMEM_BYTES);

    conv_w_kernel<<<160, 256>>>(Wq, bq, Wk, bk, Wv, bv);
    proj_mma_kernel<<<dim3(NPIX / 128, 5, BATCH), 256>>>(x);
    attn_mma<<<dim3(NPIX / 32, 2, BATCH), 128, SMEM_BYTES>>>(x, gamma, out);
}